// round 1
// baseline (speedup 1.0000x reference)
#include <cuda_runtime.h>
#include <cuda_bf16.h>
#include <math.h>

// Problem constants
#define BB 2
#define SS 2048
#define DD 1024
#define HH 16
#define DH 64
#define MM (BB*SS)          // 4096 rows
#define LAMBDA_INIT 0.8f
#define GN_EPS 1e-5f

// Scratch (device globals; no allocation allowed)
__device__ float g_Q[MM*DD];
__device__ float g_K[MM*DD];
__device__ float g_V[MM*DD];
__device__ float g_AO[MM*DD];   // attention output [B,S,H,DH]
__device__ float g_N[MM*DD];    // normalized
__device__ float g_lam[HH];
__device__ float g_mean[BB*HH];
__device__ float g_rstd[BB*HH];

// ---------------------------------------------------------------------------
// lambda[h] = exp(<lq1_h,lk1_h>) - exp(<lq2_h,lk2_h>) + 0.8
// one warp per head
// ---------------------------------------------------------------------------
__global__ void lambda_kernel(const float* __restrict__ lq1, const float* __restrict__ lk1,
                              const float* __restrict__ lq2, const float* __restrict__ lk2,
                              float* __restrict__ lam) {
    int h = threadIdx.x >> 5;
    int lane = threadIdx.x & 31;
    const float* a1 = lq1 + h * DH;
    const float* b1 = lk1 + h * DH;
    const float* a2 = lq2 + h * DH;
    const float* b2 = lk2 + h * DH;
    float s1 = a1[lane] * b1[lane] + a1[lane + 32] * b1[lane + 32];
    float s2 = a2[lane] * b2[lane] + a2[lane + 32] * b2[lane + 32];
    #pragma unroll
    for (int off = 16; off > 0; off >>= 1) {
        s1 += __shfl_xor_sync(0xffffffffu, s1, off);
        s2 += __shfl_xor_sync(0xffffffffu, s2, off);
    }
    if (lane == 0) lam[h] = expf(s1) - expf(s2) + LAMBDA_INIT;
}

// ---------------------------------------------------------------------------
// SGEMM: C[M,N] = A[M,K] @ B[K,N] + bias[N]
// 64x64 tile, BK=16, 256 threads, 4x4 per thread
// ---------------------------------------------------------------------------
__global__ __launch_bounds__(256) void sgemm_bias(
    const float* __restrict__ A, const float* __restrict__ B,
    const float* __restrict__ bias, float* __restrict__ C,
    int M, int N, int K)
{
    __shared__ float As[16][64];   // [k][m]
    __shared__ float Bs[16][64];   // [k][n]

    const int tid = threadIdx.x;
    const int tx = tid & 15;       // col group
    const int ty = tid >> 4;       // row group
    const int bx = blockIdx.x;     // N tile
    const int by = blockIdx.y;     // M tile

    const int arow = tid >> 2;           // 0..63
    const int ac   = (tid & 3) << 2;     // 0,4,8,12
    const int brow = tid >> 4;           // 0..15
    const int bc   = (tid & 15) << 2;    // 0..60

    const float* Ap = A + (size_t)(by * 64 + arow) * K + ac;
    const float* Bp = B + (size_t)brow * N + bx * 64 + bc;

    float acc[4][4];
    #pragma unroll
    for (int i = 0; i < 4; i++)
        #pragma unroll
        for (int j = 0; j < 4; j++) acc[i][j] = 0.f;

    for (int kt = 0; kt < K; kt += 16) {
        float4 a  = *(const float4*)(Ap + kt);
        float4 bv = *(const float4*)(Bp + (size_t)kt * N);
        As[ac + 0][arow] = a.x;
        As[ac + 1][arow] = a.y;
        As[ac + 2][arow] = a.z;
        As[ac + 3][arow] = a.w;
        *(float4*)&Bs[brow][bc] = bv;
        __syncthreads();
        #pragma unroll
        for (int kk = 0; kk < 16; kk++) {
            float4 af = *(const float4*)&As[kk][ty << 2];
            float4 bf = *(const float4*)&Bs[kk][tx << 2];
            acc[0][0] += af.x * bf.x; acc[0][1] += af.x * bf.y; acc[0][2] += af.x * bf.z; acc[0][3] += af.x * bf.w;
            acc[1][0] += af.y * bf.x; acc[1][1] += af.y * bf.y; acc[1][2] += af.y * bf.z; acc[1][3] += af.y * bf.w;
            acc[2][0] += af.z * bf.x; acc[2][1] += af.z * bf.y; acc[2][2] += af.z * bf.z; acc[2][3] += af.z * bf.w;
            acc[3][0] += af.w * bf.x; acc[3][1] += af.w * bf.y; acc[3][2] += af.w * bf.z; acc[3][3] += af.w * bf.w;
        }
        __syncthreads();
    }

    float4 bb = *(const float4*)(bias + bx * 64 + (tx << 2));
    #pragma unroll
    for (int i = 0; i < 4; i++) {
        int m = by * 64 + (ty << 2) + i;
        float4 out;
        out.x = acc[i][0] + bb.x;
        out.y = acc[i][1] + bb.y;
        out.z = acc[i][2] + bb.z;
        out.w = acc[i][3] + bb.w;
        *(float4*)(C + (size_t)m * N + bx * 64 + (tx << 2)) = out;
    }
}

// ---------------------------------------------------------------------------
// Flash attention: Br=Bc=64, DH=64. 256 threads = 8 warps.
// Warp w owns rows w*8..w*8+7; lane = quarter*8 + r8.
// Thread owns: S cols [q*16, q*16+16) and O dims [q*16, q*16+16) for its row.
// Row reductions + P broadcast are intra-warp shuffles.
// ---------------------------------------------------------------------------
__global__ __launch_bounds__(256) void flash_attn(
    const float* __restrict__ Q, const float* __restrict__ K,
    const float* __restrict__ V, const float* __restrict__ lam,
    float* __restrict__ O)
{
    __shared__ float Qs[64][64];   // [d][row], pre-scaled
    __shared__ float Ks[64][64];   // [d][col]
    __shared__ float Vs[64][64];   // [col][d]

    const int tid  = threadIdx.x;
    const int warp = tid >> 5;
    const int lane = tid & 31;
    const int qtr  = lane >> 3;       // 0..3
    const int r8   = lane & 7;        // 0..7
    const int row  = (warp << 3) | r8;   // 0..63
    const int c0   = qtr << 4;
    const int d0   = qtr << 4;

    const int bh = blockIdx.y;
    const int b  = bh >> 4;
    const int h  = bh & 15;
    const int i0 = blockIdx.x << 6;

    const float fac = 0.125f * lam[h];   // DH^-0.5 * lambda[h]

    // Load Q tile (transposed, pre-scaled)
    {
        const float* qp = Q + ((size_t)(b * SS + i0) * HH + h) * DH;
        #pragma unroll
        for (int i = 0; i < 4; i++) {
            int linear = tid + i * 256;
            int rr = linear >> 4;
            int dg = (linear & 15) << 2;
            float4 v = *(const float4*)(qp + (size_t)rr * (HH * DH) + dg);
            Qs[dg + 0][rr] = v.x * fac;
            Qs[dg + 1][rr] = v.y * fac;
            Qs[dg + 2][rr] = v.z * fac;
            Qs[dg + 3][rr] = v.w * fac;
        }
    }

    float o[16];
    #pragma unroll
    for (int i = 0; i < 16; i++) o[i] = 0.f;
    float m_run = -INFINITY, l_run = 0.f;

    const float* kp0 = K + ((size_t)(b * SS) * HH + h) * DH;
    const float* vp0 = V + ((size_t)(b * SS) * HH + h) * DH;

    for (int jt = 0; jt < SS / 64; jt++) {
        __syncthreads();   // previous tile's reads complete
        const float* kp = kp0 + (size_t)jt * 64 * HH * DH;
        const float* vp = vp0 + (size_t)jt * 64 * HH * DH;
        #pragma unroll
        for (int i = 0; i < 4; i++) {
            int linear = tid + i * 256;
            int rr = linear >> 4;
            int dg = (linear & 15) << 2;
            float4 kv = *(const float4*)(kp + (size_t)rr * (HH * DH) + dg);
            Ks[dg + 0][rr] = kv.x;
            Ks[dg + 1][rr] = kv.y;
            Ks[dg + 2][rr] = kv.z;
            Ks[dg + 3][rr] = kv.w;
            float4 vv = *(const float4*)(vp + (size_t)rr * (HH * DH) + dg);
            *(float4*)&Vs[rr][dg] = vv;
        }
        __syncthreads();

        // S = Q K^T (scaled): 16 columns per thread
        float s[16];
        #pragma unroll
        for (int c = 0; c < 16; c++) s[c] = 0.f;
        #pragma unroll 8
        for (int d = 0; d < 64; d++) {
            float qv = Qs[d][row];
            float4 k0 = *(const float4*)&Ks[d][c0];
            float4 k1 = *(const float4*)&Ks[d][c0 + 4];
            float4 k2 = *(const float4*)&Ks[d][c0 + 8];
            float4 k3 = *(const float4*)&Ks[d][c0 + 12];
            s[0]  += qv * k0.x; s[1]  += qv * k0.y; s[2]  += qv * k0.z; s[3]  += qv * k0.w;
            s[4]  += qv * k1.x; s[5]  += qv * k1.y; s[6]  += qv * k1.z; s[7]  += qv * k1.w;
            s[8]  += qv * k2.x; s[9]  += qv * k2.y; s[10] += qv * k2.z; s[11] += qv * k2.w;
            s[12] += qv * k3.x; s[13] += qv * k3.y; s[14] += qv * k3.z; s[15] += qv * k3.w;
        }

        // tile row-max across 4 quarter-lanes (xor 8 / 16)
        float mt = s[0];
        #pragma unroll
        for (int c = 1; c < 16; c++) mt = fmaxf(mt, s[c]);
        mt = fmaxf(mt, __shfl_xor_sync(0xffffffffu, mt, 8));
        mt = fmaxf(mt, __shfl_xor_sync(0xffffffffu, mt, 16));

        float m_new = fmaxf(m_run, mt);
        float alpha = __expf(m_run - m_new);
        float lt = 0.f;
        #pragma unroll
        for (int c = 0; c < 16; c++) {
            s[c] = __expf(s[c] - m_new);
            lt += s[c];
        }
        lt += __shfl_xor_sync(0xffffffffu, lt, 8);
        lt += __shfl_xor_sync(0xffffffffu, lt, 16);
        l_run = l_run * alpha + lt;
        m_run = m_new;
        #pragma unroll
        for (int i = 0; i < 16; i++) o[i] *= alpha;

        // O += P @ V  (P broadcast from owning quarter-lane via shuffle)
        #pragma unroll
        for (int c = 0; c < 64; c++) {
            int src = ((c >> 4) << 3) | r8;
            float pc = __shfl_sync(0xffffffffu, s[c & 15], src);
            float4 v0 = *(const float4*)&Vs[c][d0];
            float4 v1 = *(const float4*)&Vs[c][d0 + 4];
            float4 v2 = *(const float4*)&Vs[c][d0 + 8];
            float4 v3 = *(const float4*)&Vs[c][d0 + 12];
            o[0]  += pc * v0.x; o[1]  += pc * v0.y; o[2]  += pc * v0.z; o[3]  += pc * v0.w;
            o[4]  += pc * v1.x; o[5]  += pc * v1.y; o[6]  += pc * v1.z; o[7]  += pc * v1.w;
            o[8]  += pc * v2.x; o[9]  += pc * v2.y; o[10] += pc * v2.z; o[11] += pc * v2.w;
            o[12] += pc * v3.x; o[13] += pc * v3.y; o[14] += pc * v3.z; o[15] += pc * v3.w;
        }
    }

    float inv_l = 1.f / l_run;
    float* op = O + ((size_t)(b * SS + i0 + row) * HH + h) * DH + d0;
    #pragma unroll
    for (int i = 0; i < 4; i++) {
        float4 w;
        w.x = o[i * 4 + 0] * inv_l;
        w.y = o[i * 4 + 1] * inv_l;
        w.z = o[i * 4 + 2] * inv_l;
        w.w = o[i * 4 + 3] * inv_l;
        *(float4*)(op + i * 4) = w;
    }
}

// ---------------------------------------------------------------------------
// GroupNorm stats: per (b,h), mean/var over (S, DH) = 131072 elems
// ---------------------------------------------------------------------------
__global__ __launch_bounds__(256) void gn_stats(const float* __restrict__ O,
                                                float* __restrict__ mean,
                                                float* __restrict__ rstd)
{
    const int bh = blockIdx.x;
    const int b = bh >> 4;
    const int h = bh & 15;
    const float* base = O + ((size_t)b * SS * HH + h) * DH;

    double sum = 0.0, sumsq = 0.0;
    // iterate float4 groups: S*DH/4 = 32768 groups
    for (int idx = threadIdx.x; idx < SS * DH / 4; idx += 256) {
        int s_ = idx >> 4;
        int dg = (idx & 15) << 2;
        float4 v = *(const float4*)(base + (size_t)s_ * (HH * DH) + dg);
        sum   += (double)v.x + (double)v.y + (double)v.z + (double)v.w;
        sumsq += (double)v.x * v.x + (double)v.y * v.y + (double)v.z * v.z + (double)v.w * v.w;
    }
    const int lane = threadIdx.x & 31;
    const int warp = threadIdx.x >> 5;
    #pragma unroll
    for (int off = 16; off > 0; off >>= 1) {
        sum   += __shfl_xor_sync(0xffffffffu, sum, off);
        sumsq += __shfl_xor_sync(0xffffffffu, sumsq, off);
    }
    __shared__ double ws[8], wq[8];
    if (lane == 0) { ws[warp] = sum; wq[warp] = sumsq; }
    __syncthreads();
    if (threadIdx.x == 0) {
        double ts = 0.0, tq = 0.0;
        #pragma unroll
        for (int i = 0; i < 8; i++) { ts += ws[i]; tq += wq[i]; }
        double n = (double)SS * DH;
        double mu = ts / n;
        double var = tq / n - mu * mu;
        mean[bh] = (float)mu;
        rstd[bh] = (float)(1.0 / sqrt(var + (double)GN_EPS));
    }
}

// ---------------------------------------------------------------------------
// GroupNorm apply: n = (o - mean)*rstd*gw + gb, vectorized float4
// ---------------------------------------------------------------------------
__global__ __launch_bounds__(256) void gn_norm(
    const float* __restrict__ O, const float* __restrict__ mean,
    const float* __restrict__ rstd, const float* __restrict__ gw,
    const float* __restrict__ gb, float* __restrict__ Nout)
{
    int idx = blockIdx.x * 256 + threadIdx.x;     // float4 index, total 1M
    int e = idx << 2;
    int d = e & 63;
    int h = (e >> 6) & 15;
    int b = e >> 21;   // S*H*DH = 2^21
    int bh = (b << 4) | h;
    float mu = mean[bh];
    float rs = rstd[bh];
    float4 v = *(const float4*)(O + e);
    float4 w = *(const float4*)(gw + h * DH + d);
    float4 g = *(const float4*)(gb + h * DH + d);
    float4 out;
    out.x = (v.x - mu) * rs * w.x + g.x;
    out.y = (v.y - mu) * rs * w.y + g.y;
    out.z = (v.z - mu) * rs * w.z + g.z;
    out.w = (v.w - mu) * rs * w.w + g.w;
    *(float4*)(Nout + e) = out;
}

// ---------------------------------------------------------------------------
extern "C" void kernel_launch(void* const* d_in, const int* in_sizes, int n_in,
                              void* d_out, int out_size) {
    const float* x   = (const float*)d_in[0];
    const float* Wq  = (const float*)d_in[1];
    const float* bq  = (const float*)d_in[2];
    const float* Wk  = (const float*)d_in[3];
    const float* bk  = (const float*)d_in[4];
    const float* Wv  = (const float*)d_in[5];
    const float* bv  = (const float*)d_in[6];
    const float* Wo  = (const float*)d_in[7];
    const float* bo  = (const float*)d_in[8];
    const float* lq1 = (const float*)d_in[9];
    const float* lk1 = (const float*)d_in[10];
    const float* lq2 = (const float*)d_in[11];
    const float* lk2 = (const float*)d_in[12];
    const float* gnw = (const float*)d_in[13];
    const float* gnb = (const float*)d_in[14];
    float* y = (float*)d_out;

    float *Qp, *Kp, *Vp, *AOp, *Np, *lamp, *meanp, *rstdp;
    cudaGetSymbolAddress((void**)&Qp,    g_Q);
    cudaGetSymbolAddress((void**)&Kp,    g_K);
    cudaGetSymbolAddress((void**)&Vp,    g_V);
    cudaGetSymbolAddress((void**)&AOp,   g_AO);
    cudaGetSymbolAddress((void**)&Np,    g_N);
    cudaGetSymbolAddress((void**)&lamp,  g_lam);
    cudaGetSymbolAddress((void**)&meanp, g_mean);
    cudaGetSymbolAddress((void**)&rstdp, g_rstd);

    lambda_kernel<<<1, HH * 32>>>(lq1, lk1, lq2, lk2, lamp);

    dim3 gemmGrid(DD / 64, MM / 64);   // (16, 64)
    sgemm_bias<<<gemmGrid, 256>>>(x, Wq, bq, Qp, MM, DD, DD);
    sgemm_bias<<<gemmGrid, 256>>>(x, Wk, bk, Kp, MM, DD, DD);
    sgemm_bias<<<gemmGrid, 256>>>(x, Wv, bv, Vp, MM, DD, DD);

    flash_attn<<<dim3(SS / 64, BB * HH), 256>>>(Qp, Kp, Vp, lamp, AOp);

    gn_stats<<<BB * HH, 256>>>(AOp, meanp, rstdp);
    gn_norm<<<(MM * DD / 4) / 256, 256>>>(AOp, meanp, rstdp, gnw, gnb, Np);

    sgemm_bias<<<gemmGrid, 256>>>(Np, Wo, bo, y, MM, DD, DD);
}

// round 2
// speedup vs baseline: 3.1613x; 3.1613x over previous
#include <cuda_runtime.h>
#include <math.h>

// Problem constants
#define BB 2
#define SS 2048
#define DD 1024
#define HH 16
#define DHH 64
#define MM (BB*SS)          // 4096 rows
#define LAMBDA_INIT 0.8f
#define GN_EPS 1e-5f

// Scratch (device globals; no allocation allowed)
__device__ float g_Q[MM*DD];
__device__ float g_K[MM*DD];
__device__ float g_V[MM*DD];
__device__ float g_AO[MM*DD];   // attention output [B,S,H,DH]
__device__ float g_lam[HH];
__device__ float g_mean[BB*HH];
__device__ float g_rstd[BB*HH];

// ---------------------------------------------------------------------------
// helpers: tf32 convert + m16n8k8 tf32 mma
// ---------------------------------------------------------------------------
__device__ __forceinline__ float to_tf32(float x) {
    unsigned u;
    asm("cvt.rna.tf32.f32 %0, %1;" : "=r"(u) : "f"(x));
    return __uint_as_float(u);
}

__device__ __forceinline__ void mma_tf32(float* c, const float* a, const float* b) {
    const unsigned* A = reinterpret_cast<const unsigned*>(a);
    const unsigned* B = reinterpret_cast<const unsigned*>(b);
    asm volatile(
        "mma.sync.aligned.m16n8k8.row.col.f32.tf32.tf32.f32 "
        "{%0,%1,%2,%3}, {%4,%5,%6,%7}, {%8,%9}, {%0,%1,%2,%3};\n"
        : "+f"(c[0]), "+f"(c[1]), "+f"(c[2]), "+f"(c[3])
        : "r"(A[0]), "r"(A[1]), "r"(A[2]), "r"(A[3]),
          "r"(B[0]), "r"(B[1]));
}

// ---------------------------------------------------------------------------
// lambda[h] = exp(<lq1_h,lk1_h>) - exp(<lq2_h,lk2_h>) + 0.8  (one warp/head)
// ---------------------------------------------------------------------------
__global__ void lambda_kernel(const float* __restrict__ lq1, const float* __restrict__ lk1,
                              const float* __restrict__ lq2, const float* __restrict__ lk2,
                              float* __restrict__ lam) {
    int h = threadIdx.x >> 5;
    int lane = threadIdx.x & 31;
    const float* a1 = lq1 + h * DHH;
    const float* b1 = lk1 + h * DHH;
    const float* a2 = lq2 + h * DHH;
    const float* b2 = lk2 + h * DHH;
    float s1 = a1[lane] * b1[lane] + a1[lane + 32] * b1[lane + 32];
    float s2 = a2[lane] * b2[lane] + a2[lane + 32] * b2[lane + 32];
    #pragma unroll
    for (int off = 16; off > 0; off >>= 1) {
        s1 += __shfl_xor_sync(0xffffffffu, s1, off);
        s2 += __shfl_xor_sync(0xffffffffu, s2, off);
    }
    if (lane == 0) lam[h] = expf(s1) - expf(s2) + LAMBDA_INIT;
}

// ---------------------------------------------------------------------------
// tf32 tensor-core GEMM: C[M,N] = A @ B + bias.  BM=128 BN=128 BK=16,
// 256 threads = 8 warps (2x4), warp tile 64x32, double-buffered smem.
// FUSE=1: A element = ((A - mean[b,h]) * rstd[b,h]) * gnw[k] + gnb[k]
// ---------------------------------------------------------------------------
template<int FUSE>
__global__ __launch_bounds__(256) void gemm_tf32(
    const float* __restrict__ A, const float* __restrict__ B,
    const float* __restrict__ bias, float* __restrict__ C,
    int M, int N, int K,
    const float* __restrict__ mean, const float* __restrict__ rstd,
    const float* __restrict__ gnw, const float* __restrict__ gnb)
{
    __shared__ float As[2][128][20];   // [m][k], stride 20 -> conflict-free frags
    __shared__ float Bs[2][16][136];   // [k][n], stride 136 -> conflict-free frags

    const int tid  = threadIdx.x;
    const int warp = tid >> 5;
    const int lane = tid & 31;
    const int g    = lane >> 2;
    const int tig  = lane & 3;
    const int wm   = warp >> 2;    // 0..1
    const int wn   = warp & 3;     // 0..3
    const int bm   = blockIdx.y * 128;
    const int bn   = blockIdx.x * 128;

    int arow[2], akc[2], bkr[2], bnc[2];
    #pragma unroll
    for (int i = 0; i < 2; i++) {
        int idx = tid + i * 256;
        arow[i] = idx >> 2;          // 0..127
        akc[i]  = (idx & 3) << 2;    // 0,4,8,12
        bkr[i]  = idx >> 5;          // 0..15
        bnc[i]  = (idx & 31) << 2;   // 0..124
    }

    float c[4][4][4];
    #pragma unroll
    for (int mt = 0; mt < 4; mt++)
        #pragma unroll
        for (int nt = 0; nt < 4; nt++)
            #pragma unroll
            for (int r = 0; r < 4; r++) c[mt][nt][r] = 0.f;

    float4 fa[2], fb[2];
    const int NT = K / 16;

    // fetch tile kt into registers
    auto do_fetch = [&](int kt) {
        #pragma unroll
        for (int i = 0; i < 2; i++) {
            fa[i] = *(const float4*)(A + (size_t)(bm + arow[i]) * K + kt + akc[i]);
            if (FUSE) {
                int rowg = bm + arow[i];
                int bi   = rowg >> 11;          // row / 2048
                int k    = kt + akc[i];
                int hh   = k >> 6;
                float mu = mean[bi * HH + hh];
                float rs = rstd[bi * HH + hh];
                float4 w  = *(const float4*)(gnw + k);
                float4 gb = *(const float4*)(gnb + k);
                fa[i].x = (fa[i].x - mu) * rs * w.x + gb.x;
                fa[i].y = (fa[i].y - mu) * rs * w.y + gb.y;
                fa[i].z = (fa[i].z - mu) * rs * w.z + gb.z;
                fa[i].w = (fa[i].w - mu) * rs * w.w + gb.w;
            }
            fb[i] = *(const float4*)(B + (size_t)(kt + bkr[i]) * N + bn + bnc[i]);
        }
    };
    auto do_store = [&](int buf) {
        #pragma unroll
        for (int i = 0; i < 2; i++) {
            As[buf][arow[i]][akc[i] + 0] = to_tf32(fa[i].x);
            As[buf][arow[i]][akc[i] + 1] = to_tf32(fa[i].y);
            As[buf][arow[i]][akc[i] + 2] = to_tf32(fa[i].z);
            As[buf][arow[i]][akc[i] + 3] = to_tf32(fa[i].w);
            Bs[buf][bkr[i]][bnc[i] + 0] = to_tf32(fb[i].x);
            Bs[buf][bkr[i]][bnc[i] + 1] = to_tf32(fb[i].y);
            Bs[buf][bkr[i]][bnc[i] + 2] = to_tf32(fb[i].z);
            Bs[buf][bkr[i]][bnc[i] + 3] = to_tf32(fb[i].w);
        }
    };

    do_fetch(0);
    do_store(0);
    __syncthreads();

    for (int t = 0; t < NT; t++) {
        int buf = t & 1;
        if (t + 1 < NT) do_fetch((t + 1) * 16);

        #pragma unroll
        for (int kk = 0; kk < 16; kk += 8) {
            float a[4][4], b[4][2];
            #pragma unroll
            for (int mt = 0; mt < 4; mt++) {
                int r0 = wm * 64 + mt * 16 + g;
                a[mt][0] = As[buf][r0][kk + tig];
                a[mt][1] = As[buf][r0 + 8][kk + tig];
                a[mt][2] = As[buf][r0][kk + tig + 4];
                a[mt][3] = As[buf][r0 + 8][kk + tig + 4];
            }
            #pragma unroll
            for (int nt = 0; nt < 4; nt++) {
                int cn = wn * 32 + nt * 8 + g;
                b[nt][0] = Bs[buf][kk + tig][cn];
                b[nt][1] = Bs[buf][kk + tig + 4][cn];
            }
            #pragma unroll
            for (int mt = 0; mt < 4; mt++)
                #pragma unroll
                for (int nt = 0; nt < 4; nt++)
                    mma_tf32(c[mt][nt], a[mt], b[nt]);
        }

        if (t + 1 < NT) do_store(buf ^ 1);
        __syncthreads();
    }

    // epilogue + bias
    #pragma unroll
    for (int mt = 0; mt < 4; mt++) {
        int row = bm + wm * 64 + mt * 16 + g;
        #pragma unroll
        for (int nt = 0; nt < 4; nt++) {
            int col = bn + wn * 32 + nt * 8 + 2 * tig;
            float2 bb = *(const float2*)(bias + col);
            float2 o0 = make_float2(c[mt][nt][0] + bb.x, c[mt][nt][1] + bb.y);
            float2 o1 = make_float2(c[mt][nt][2] + bb.x, c[mt][nt][3] + bb.y);
            *(float2*)(C + (size_t)row * N + col) = o0;
            *(float2*)(C + (size_t)(row + 8) * N + col) = o1;
        }
    }
}

// ---------------------------------------------------------------------------
// tf32 tensor-core flash attention. Br=Bc=64, DH=64.
// 128 threads = 4 warps; warp w owns query rows [16w,16w+16) of the tile.
// QK^T and PV both via mma.m16n8k8.tf32; P round-trips via warp-private smem.
// ---------------------------------------------------------------------------
__global__ __launch_bounds__(128) void flash_tf32(
    const float* __restrict__ Q, const float* __restrict__ K,
    const float* __restrict__ V, const float* __restrict__ lam,
    float* __restrict__ O)
{
    extern __shared__ float smf[];
    float (*Qs)[68] = (float(*)[68])(smf);                       // [row][dh]
    float (*Ks)[68] = (float(*)[68])(smf + 64 * 68);             // [j][dh]
    float (*Ps)[68] = (float(*)[68])(smf + 2 * 64 * 68);         // [row][j]
    float (*Vs)[72] = (float(*)[72])(smf + 3 * 64 * 68);         // [j][dh]

    const int tid  = threadIdx.x;
    const int warp = tid >> 5;
    const int lane = tid & 31;
    const int g    = lane >> 2;
    const int tig  = lane & 3;
    const int r_q  = (warp << 4) + g;      // local row (and +8)

    const int bh = blockIdx.y;
    const int b  = bh >> 4;
    const int h  = bh & 15;
    const int i0 = blockIdx.x << 6;

    const float fac = 0.125f * lam[h];

    // load Q tile (scaled, tf32)
    {
        const float* qp = Q + (size_t)(b * SS + i0) * DD + h * DHH;
        #pragma unroll
        for (int i = 0; i < 8; i++) {
            int idx = tid + i * 128;
            int r = idx >> 4, dg = (idx & 15) << 2;
            float4 v = *(const float4*)(qp + (size_t)r * DD + dg);
            Qs[r][dg + 0] = to_tf32(v.x * fac);
            Qs[r][dg + 1] = to_tf32(v.y * fac);
            Qs[r][dg + 2] = to_tf32(v.z * fac);
            Qs[r][dg + 3] = to_tf32(v.w * fac);
        }
    }

    float o[8][4];
    #pragma unroll
    for (int nt = 0; nt < 8; nt++)
        #pragma unroll
        for (int r = 0; r < 4; r++) o[nt][r] = 0.f;
    float m0 = -INFINITY, m1 = -INFINITY, l0 = 0.f, l1 = 0.f;

    const float* kp0 = K + (size_t)b * SS * DD + h * DHH;
    const float* vp0 = V + (size_t)b * SS * DD + h * DHH;

    for (int jt = 0; jt < SS / 64; jt++) {
        __syncthreads();
        const float* kp = kp0 + (size_t)jt * 64 * DD;
        const float* vp = vp0 + (size_t)jt * 64 * DD;
        #pragma unroll
        for (int i = 0; i < 8; i++) {
            int idx = tid + i * 128;
            int r = idx >> 4, dg = (idx & 15) << 2;
            float4 kv = *(const float4*)(kp + (size_t)r * DD + dg);
            Ks[r][dg + 0] = to_tf32(kv.x);
            Ks[r][dg + 1] = to_tf32(kv.y);
            Ks[r][dg + 2] = to_tf32(kv.z);
            Ks[r][dg + 3] = to_tf32(kv.w);
            float4 vv = *(const float4*)(vp + (size_t)r * DD + dg);
            Vs[r][dg + 0] = to_tf32(vv.x);
            Vs[r][dg + 1] = to_tf32(vv.y);
            Vs[r][dg + 2] = to_tf32(vv.z);
            Vs[r][dg + 3] = to_tf32(vv.w);
        }
        __syncthreads();

        // S = Q K^T  (8 n-tiles of 8 cols each)
        float s[8][4];
        #pragma unroll
        for (int nt = 0; nt < 8; nt++)
            #pragma unroll
            for (int r = 0; r < 4; r++) s[nt][r] = 0.f;

        #pragma unroll
        for (int kk = 0; kk < 64; kk += 8) {
            float a[4];
            a[0] = Qs[r_q][kk + tig];
            a[1] = Qs[r_q + 8][kk + tig];
            a[2] = Qs[r_q][kk + tig + 4];
            a[3] = Qs[r_q + 8][kk + tig + 4];
            #pragma unroll
            for (int nt = 0; nt < 8; nt++) {
                float bfr[2];
                bfr[0] = Ks[nt * 8 + g][kk + tig];
                bfr[1] = Ks[nt * 8 + g][kk + tig + 4];
                mma_tf32(s[nt], a, bfr);
            }
        }

        // online softmax for rows r_q (regs 0,1) and r_q+8 (regs 2,3)
        float mx0 = -INFINITY, mx1 = -INFINITY;
        #pragma unroll
        for (int nt = 0; nt < 8; nt++) {
            mx0 = fmaxf(mx0, fmaxf(s[nt][0], s[nt][1]));
            mx1 = fmaxf(mx1, fmaxf(s[nt][2], s[nt][3]));
        }
        mx0 = fmaxf(mx0, __shfl_xor_sync(0xffffffffu, mx0, 1));
        mx0 = fmaxf(mx0, __shfl_xor_sync(0xffffffffu, mx0, 2));
        mx1 = fmaxf(mx1, __shfl_xor_sync(0xffffffffu, mx1, 1));
        mx1 = fmaxf(mx1, __shfl_xor_sync(0xffffffffu, mx1, 2));

        float mn0 = fmaxf(m0, mx0);
        float mn1 = fmaxf(m1, mx1);
        float al0 = __expf(m0 - mn0);
        float al1 = __expf(m1 - mn1);
        float lt0 = 0.f, lt1 = 0.f;
        #pragma unroll
        for (int nt = 0; nt < 8; nt++) {
            s[nt][0] = __expf(s[nt][0] - mn0); lt0 += s[nt][0];
            s[nt][1] = __expf(s[nt][1] - mn0); lt0 += s[nt][1];
            s[nt][2] = __expf(s[nt][2] - mn1); lt1 += s[nt][2];
            s[nt][3] = __expf(s[nt][3] - mn1); lt1 += s[nt][3];
        }
        lt0 += __shfl_xor_sync(0xffffffffu, lt0, 1);
        lt0 += __shfl_xor_sync(0xffffffffu, lt0, 2);
        lt1 += __shfl_xor_sync(0xffffffffu, lt1, 1);
        lt1 += __shfl_xor_sync(0xffffffffu, lt1, 2);
        l0 = l0 * al0 + lt0;
        l1 = l1 * al1 + lt1;
        m0 = mn0;
        m1 = mn1;
        #pragma unroll
        for (int nt = 0; nt < 8; nt++) {
            o[nt][0] *= al0; o[nt][1] *= al0;
            o[nt][2] *= al1; o[nt][3] *= al1;
        }

        // P -> warp-private smem rows (tf32)
        #pragma unroll
        for (int nt = 0; nt < 8; nt++) {
            Ps[r_q][nt * 8 + 2 * tig]         = to_tf32(s[nt][0]);
            Ps[r_q][nt * 8 + 2 * tig + 1]     = to_tf32(s[nt][1]);
            Ps[r_q + 8][nt * 8 + 2 * tig]     = to_tf32(s[nt][2]);
            Ps[r_q + 8][nt * 8 + 2 * tig + 1] = to_tf32(s[nt][3]);
        }
        __syncwarp();

        // O += P @ V
        #pragma unroll
        for (int kk = 0; kk < 64; kk += 8) {
            float a[4];
            a[0] = Ps[r_q][kk + tig];
            a[1] = Ps[r_q + 8][kk + tig];
            a[2] = Ps[r_q][kk + tig + 4];
            a[3] = Ps[r_q + 8][kk + tig + 4];
            #pragma unroll
            for (int nt = 0; nt < 8; nt++) {
                float bfr[2];
                bfr[0] = Vs[kk + tig][nt * 8 + g];
                bfr[1] = Vs[kk + tig + 4][nt * 8 + g];
                mma_tf32(o[nt], a, bfr);
            }
        }
    }

    float inv0 = 1.f / l0;
    float inv1 = 1.f / l1;
    float* op0 = O + (size_t)(b * SS + i0 + r_q) * DD + h * DHH;
    float* op1 = op0 + 8 * DD;
    #pragma unroll
    for (int nt = 0; nt < 8; nt++) {
        *(float2*)(op0 + nt * 8 + 2 * tig) =
            make_float2(o[nt][0] * inv0, o[nt][1] * inv0);
        *(float2*)(op1 + nt * 8 + 2 * tig) =
            make_float2(o[nt][2] * inv1, o[nt][3] * inv1);
    }
}

// ---------------------------------------------------------------------------
// GroupNorm stats: per (b,h), mean/var over (S, DH) = 131072 elems
// ---------------------------------------------------------------------------
__global__ __launch_bounds__(256) void gn_stats(const float* __restrict__ O,
                                                float* __restrict__ mean,
                                                float* __restrict__ rstd)
{
    const int bh = blockIdx.x;
    const int b = bh >> 4;
    const int h = bh & 15;
    const float* base = O + ((size_t)b * SS * HH + h) * DHH;

    double sum = 0.0, sumsq = 0.0;
    for (int idx = threadIdx.x; idx < SS * DHH / 4; idx += 256) {
        int s_ = idx >> 4;
        int dg = (idx & 15) << 2;
        float4 v = *(const float4*)(base + (size_t)s_ * DD + dg);
        sum   += (double)v.x + (double)v.y + (double)v.z + (double)v.w;
        sumsq += (double)v.x * v.x + (double)v.y * v.y + (double)v.z * v.z + (double)v.w * v.w;
    }
    const int lane = threadIdx.x & 31;
    const int warp = threadIdx.x >> 5;
    #pragma unroll
    for (int off = 16; off > 0; off >>= 1) {
        sum   += __shfl_xor_sync(0xffffffffu, sum, off);
        sumsq += __shfl_xor_sync(0xffffffffu, sumsq, off);
    }
    __shared__ double ws[8], wq[8];
    if (lane == 0) { ws[warp] = sum; wq[warp] = sumsq; }
    __syncthreads();
    if (threadIdx.x == 0) {
        double ts = 0.0, tq = 0.0;
        #pragma unroll
        for (int i = 0; i < 8; i++) { ts += ws[i]; tq += wq[i]; }
        double n = (double)SS * DHH;
        double mu = ts / n;
        double var = tq / n - mu * mu;
        mean[bh] = (float)mu;
        rstd[bh] = (float)(1.0 / sqrt(var + (double)GN_EPS));
    }
}

// ---------------------------------------------------------------------------
extern "C" void kernel_launch(void* const* d_in, const int* in_sizes, int n_in,
                              void* d_out, int out_size) {
    const float* x   = (const float*)d_in[0];
    const float* Wq  = (const float*)d_in[1];
    const float* bq  = (const float*)d_in[2];
    const float* Wk  = (const float*)d_in[3];
    const float* bk  = (const float*)d_in[4];
    const float* Wv  = (const float*)d_in[5];
    const float* bv  = (const float*)d_in[6];
    const float* Wo  = (const float*)d_in[7];
    const float* bo  = (const float*)d_in[8];
    const float* lq1 = (const float*)d_in[9];
    const float* lk1 = (const float*)d_in[10];
    const float* lq2 = (const float*)d_in[11];
    const float* lk2 = (const float*)d_in[12];
    const float* gnw = (const float*)d_in[13];
    const float* gnb = (const float*)d_in[14];
    float* y = (float*)d_out;

    float *Qp, *Kp, *Vp, *AOp, *lamp, *meanp, *rstdp;
    cudaGetSymbolAddress((void**)&Qp,    g_Q);
    cudaGetSymbolAddress((void**)&Kp,    g_K);
    cudaGetSymbolAddress((void**)&Vp,    g_V);
    cudaGetSymbolAddress((void**)&AOp,   g_AO);
    cudaGetSymbolAddress((void**)&lamp,  g_lam);
    cudaGetSymbolAddress((void**)&meanp, g_mean);
    cudaGetSymbolAddress((void**)&rstdp, g_rstd);

    static int smem_set = 0;
    if (!smem_set) {
        cudaFuncSetAttribute(flash_tf32, cudaFuncAttributeMaxDynamicSharedMemorySize,
                             (3 * 64 * 68 + 64 * 72) * 4);
        smem_set = 1;
    }

    lambda_kernel<<<1, HH * 32>>>(lq1, lk1, lq2, lk2, lamp);

    dim3 gemmGrid(DD / 128, MM / 128);   // (8, 32)
    gemm_tf32<0><<<gemmGrid, 256>>>(x, Wq, bq, Qp, MM, DD, DD, nullptr, nullptr, nullptr, nullptr);
    gemm_tf32<0><<<gemmGrid, 256>>>(x, Wk, bk, Kp, MM, DD, DD, nullptr, nullptr, nullptr, nullptr);
    gemm_tf32<0><<<gemmGrid, 256>>>(x, Wv, bv, Vp, MM, DD, DD, nullptr, nullptr, nullptr, nullptr);

    flash_tf32<<<dim3(SS / 64, BB * HH), 128, (3 * 64 * 68 + 64 * 72) * 4>>>(Qp, Kp, Vp, lamp, AOp);

    gn_stats<<<BB * HH, 256>>>(AOp, meanp, rstdp);

    gemm_tf32<1><<<gemmGrid, 256>>>(AOp, Wo, bo, y, MM, DD, DD, meanp, rstdp, gnw, gnb);
}